// round 15
// baseline (speedup 1.0000x reference)
#include <cuda_runtime.h>
#include <cuda_bf16.h>

#define N_USERS 100000
#define N_ITEMS 50000
#define N_TOTAL (N_USERS + N_ITEMS)
#define D 64
#define DH 32                 // bf16x2 words per row (128B = one L2 line)
#define HYPER_X 0.5f
#define MAX_NNZ 2000000
#define MAX_SAMPLED 32768
#define SCAN_BLK 1024
#define SCAN_NB ((N_TOTAL + SCAN_BLK - 1) / SCAN_BLK)   // 147

// bf16x2 feature tables stored as raw uint32 words
__device__ unsigned g_h0[N_TOTAL * DH];   // converted input embeddings
__device__ unsigned g_h1[N_TOTAL * DH];
__device__ unsigned g_h2[N_TOTAL * DH];
__device__ unsigned g_h3[N_TOTAL * DH];

// CSR scratch. INVARIANT: g_deg, g_flag, g_blocksum, g_rowcount are ZERO at
// kernel_launch entry — zero-initialized at module load, re-zeroed at the end
// of every launch (inside epilogue_kernel), so graph replays are safe.
__device__ int  g_deg[N_TOTAL];
__device__ int  g_offs[N_TOTAL + 1];
__device__ int  g_rank[MAX_NNZ];         // per-edge within-row rank (from hist atomics)
__device__ int  g_blocksum[SCAN_NB];     // lookback slots: 0 = not ready, else agg+1
__device__ __align__(16) int2 g_csr[MAX_NNZ];   // {col, float_as_int(val)}

// sampled-row dedup for masked layer 3
__device__ int g_flag[N_TOTAL];
__device__ int g_rowlist[MAX_SAMPLED];
__device__ int g_rowcount;

// bf16x2 word -> 2 floats: pure ALU (SHF + LOP3), no CVT
__device__ __forceinline__ float2 bf2f(unsigned w) {
    float2 r;
    r.x = __uint_as_float(w << 16);
    r.y = __uint_as_float(w & 0xFFFF0000u);
    return r;
}
// 2 floats -> bf16x2 word (single cvt.rn.bf16x2.f32)
__device__ __forceinline__ unsigned f2bf(float a, float b) {
    __nv_bfloat162 p = __floats2bfloat162_rn(a, b);
    return *reinterpret_cast<unsigned*>(&p);
}

// ---------------------------------------------------------------------------
// FUSED: fp32->bf16 embedding convert + sampled-row mark + degree histogram.
// ---------------------------------------------------------------------------
__global__ void convert_mark_hist_kernel(const float2* __restrict__ eu,
                                         const float2* __restrict__ ei,
                                         const int* __restrict__ users,
                                         const int* __restrict__ items, int B,
                                         const int* __restrict__ row, int nnz) {
    const int i = blockIdx.x * blockDim.x + threadIdx.x;
    const int nthreads = gridDim.x * blockDim.x;

    if (i < B) {
        int u = users[i];
        if (atomicExch(&g_flag[u], 1) == 0) {
            int p = atomicAdd(&g_rowcount, 1);
            g_rowlist[p] = u;
        }
        int it = N_USERS + items[i];
        if (atomicExch(&g_flag[it], 1) == 0) {
            int p = atomicAdd(&g_rowcount, 1);
            g_rowlist[p] = it;
        }
    }

    int base = 4 * i;
    if (base + 3 < nnz) {
        int4 r4 = ((const int4*)row)[i];
        int4 k4;
        k4.x = atomicAdd(&g_deg[r4.x], 1);
        k4.y = atomicAdd(&g_deg[r4.y], 1);
        k4.z = atomicAdd(&g_deg[r4.z], 1);
        k4.w = atomicAdd(&g_deg[r4.w], 1);
        ((int4*)g_rank)[i] = k4;
    } else {
        for (int e = base; e < nnz; e++)
            g_rank[e] = atomicAdd(&g_deg[row[e]], 1);
    }

    const int total = N_TOTAL * DH;
    for (int k = i; k < total; k += nthreads) {
        float2 v = (k < N_USERS * DH) ? __ldg(&eu[k]) : __ldg(&ei[k - N_USERS * DH]);
        g_h0[k] = f2bf(v.x, v.y);
    }
}

// ---------------------------------------------------------------------------
// single-kernel exclusive scan with decoupled lookback (147 blocks, 1 wave)
// ---------------------------------------------------------------------------
__device__ __forceinline__ int block_exscan(int v, int* sh) {
    int lane = threadIdx.x & 31, wid = threadIdx.x >> 5;
    int incl = v;
    #pragma unroll
    for (int o = 1; o < 32; o <<= 1) {
        int n = __shfl_up_sync(0xffffffffu, incl, o);
        if (lane >= o) incl += n;
    }
    if (lane == 31) sh[wid] = incl;
    __syncthreads();
    if (wid == 0) {
        int w = sh[lane];
        #pragma unroll
        for (int o = 1; o < 32; o <<= 1) {
            int n = __shfl_up_sync(0xffffffffu, w, o);
            if (lane >= o) w += n;
        }
        sh[lane] = w;
    }
    __syncthreads();
    int warpoff = (wid > 0) ? sh[wid - 1] : 0;
    return warpoff + incl - v;
}

__global__ void scan_lookback_kernel() {
    __shared__ int sh[32];
    __shared__ int base_sh;
    const int t = threadIdx.x;
    const int i = blockIdx.x * SCAN_BLK + t;
    int v = (i < N_TOTAL) ? g_deg[i] : 0;
    int ex = block_exscan(v, sh);

    if (t == SCAN_BLK - 1) {
        atomicExch(&g_blocksum[blockIdx.x], ex + v + 1);
    }
    if (t == 0) base_sh = 0;
    __syncthreads();

    if (t < blockIdx.x) {
        int a;
        do { a = atomicAdd(&g_blocksum[t], 0); } while (a == 0);
        atomicAdd(&base_sh, a - 1);
    }
    __syncthreads();

    int exg = ex + base_sh;
    if (i < N_TOTAL) {
        g_offs[i] = exg;
        if (i == N_TOTAL - 1) g_offs[N_TOTAL] = exg + v;
    }
}

// ---------------------------------------------------------------------------
// CSR fill, ATOMIC-FREE: pos = offs[row] + rank (rank captured during hist).
// ---------------------------------------------------------------------------
__global__ void fill_kernel(const int* __restrict__ row,
                            const int* __restrict__ col,
                            const float* __restrict__ val, int nnz) {
    int t = blockIdx.x * blockDim.x + threadIdx.x;
    int base = 4 * t;
    if (base + 3 < nnz) {
        int4   r4 = ((const int4*)row)[t];
        int4   c4 = ((const int4*)col)[t];
        float4 v4 = ((const float4*)val)[t];
        int4   k4 = ((const int4*)g_rank)[t];
        int p0 = __ldg(&g_offs[r4.x]) + k4.x;
        int p1 = __ldg(&g_offs[r4.y]) + k4.y;
        int p2 = __ldg(&g_offs[r4.z]) + k4.z;
        int p3 = __ldg(&g_offs[r4.w]) + k4.w;
        g_csr[p0] = make_int2(c4.x, __float_as_int(v4.x));
        g_csr[p1] = make_int2(c4.y, __float_as_int(v4.y));
        g_csr[p2] = make_int2(c4.z, __float_as_int(v4.z));
        g_csr[p3] = make_int2(c4.w, __float_as_int(v4.w));
    } else {
        for (int e = base; e < nnz; e++) {
            int p = __ldg(&g_offs[row[e]]) + g_rank[e];
            g_csr[p] = make_int2(col[e], __float_as_int(val[e]));
        }
    }
}

// ---------------------------------------------------------------------------
// SpMM (bf16 storage, fp32 accumulate): 1 warp per row, one bf16x2 per lane.
// Decode is SHF+LOP3 (full-rate ALU), no F2F. Plain x2 loop + scalar tail —
// the empirically optimal loop form (R9/R12/R14).
// ---------------------------------------------------------------------------
__device__ __forceinline__ void spmm_row_bf(
        int r, int lane,
        const unsigned* __restrict__ x, unsigned* __restrict__ y) {
    const int beg = g_offs[r];
    const int end = g_offs[r + 1];

    float ax = 0.f, ay = 0.f;
    int j = beg;
    for (; j + 1 < end; j += 2) {
        int2 m0 = g_csr[j];
        int2 m1 = g_csr[j + 1];
        unsigned w0 = __ldg(&x[(long)m0.x * DH + lane]);
        unsigned w1 = __ldg(&x[(long)m1.x * DH + lane]);
        float v0 = __int_as_float(m0.y);
        float v1 = __int_as_float(m1.y);
        float2 x0 = bf2f(w0);
        float2 x1 = bf2f(w1);
        ax += v0 * x0.x; ay += v0 * x0.y;
        ax += v1 * x1.x; ay += v1 * x1.y;
    }
    if (j < end) {
        int2 m = g_csr[j];
        unsigned w = __ldg(&x[(long)m.x * DH + lane]);
        float v = __int_as_float(m.y);
        float2 xv = bf2f(w);
        ax += v * xv.x; ay += v * xv.y;
    }
    y[(long)r * DH + lane] = f2bf(ax, ay);
}

__global__ void spmm_h_kernel(const unsigned* __restrict__ x,
                              unsigned* __restrict__ y) {
    const int lane = threadIdx.x & 31;
    const int r = (blockIdx.x * blockDim.x + threadIdx.x) >> 5;
    if (r >= N_TOTAL) return;
    spmm_row_bf(r, lane, x, y);
}

// layer 3: only sampled rows
__global__ void spmm_list_kernel(const unsigned* __restrict__ x,
                                 unsigned* __restrict__ y) {
    const int lane = threadIdx.x & 31;
    const int idx = (blockIdx.x * blockDim.x + threadIdx.x) >> 5;
    if (idx >= g_rowcount) return;
    const int r = g_rowlist[idx];
    spmm_row_bf(r, lane, x, y);
}

// ---------------------------------------------------------------------------
// Epilogue: e0 from fp32 inputs (exact), e1..e3 from bf16 tables.
// ALSO restores the zeroed-state invariant (fused cleanup).
// ---------------------------------------------------------------------------
#define SAMPLES_PER_BLOCK 8

__device__ __forceinline__ float sigmoidf_(float x) {
    return 1.0f / (1.0f + expf(-x));
}

__global__ void epilogue_kernel(const float* __restrict__ emb_user,
                                const float* __restrict__ emb_item,
                                const float* __restrict__ w_user,
                                const float* __restrict__ w_item,
                                const float* __restrict__ xij_emb1,
                                const float* __restrict__ xij_emb0,
                                const int* __restrict__ users,
                                const int* __restrict__ items,
                                const int* __restrict__ xij,
                                float* __restrict__ out,
                                int B) {
    __shared__ float ws_u[D * D];                 // transposed
    __shared__ float ws_i[D * D];
    __shared__ float su[SAMPLES_PER_BLOCK][D];
    __shared__ float si[SAMPLES_PER_BLOCK][D];

    // fused cleanup: restore zeroed invariant for next graph replay
    const int gi = blockIdx.x * blockDim.x + threadIdx.x;
    if (gi < N_TOTAL) { g_deg[gi] = 0; g_flag[gi] = 0; }
    if (gi < SCAN_NB) g_blocksum[gi] = 0;
    if (gi == 0) g_rowcount = 0;

    const int tid = threadIdx.x;
    for (int idx = tid; idx < D * D; idx += blockDim.x) {
        int d = idx >> 6, k = idx & 63;
        ws_u[k * D + d] = w_user[idx];
        ws_i[k * D + d] = w_item[idx];
    }

    const int w    = tid >> 5;
    const int lane = tid & 31;
    const int s    = blockIdx.x * SAMPLES_PER_BLOCK + w;

    int item = 0;
    if (s < B) {
        int urow = users[s];
        item = items[s];
        int irow = N_USERS + item;

        long uo = (long)urow * DH + lane;
        long io = (long)irow * DH + lane;
        float2 u0 = *(const float2*)&emb_user[(long)urow * D + 2 * lane];
        float2 i0 = *(const float2*)&emb_item[(long)item * D + 2 * lane];
        float2 u1 = bf2f(g_h1[uo]);
        float2 u2 = bf2f(g_h2[uo]);
        float2 u3 = bf2f(g_h3[uo]);
        float2 i1 = bf2f(g_h1[io]);
        float2 i2 = bf2f(g_h2[io]);
        float2 i3 = bf2f(g_h3[io]);
        su[w][2 * lane]     = 0.25f * (u0.x + u1.x + u2.x + u3.x);
        su[w][2 * lane + 1] = 0.25f * (u0.y + u1.y + u2.y + u3.y);
        si[w][2 * lane]     = 0.25f * (i0.x + i1.x + i2.x + i3.x);
        si[w][2 * lane + 1] = 0.25f * (i0.y + i1.y + i2.y + i3.y);
    }
    __syncthreads();
    if (s >= B) return;

    float au0 = 0.f, au1 = 0.f, ai0 = 0.f, ai1 = 0.f;
    #pragma unroll
    for (int k = 0; k < D; k++) {
        float uk = su[w][k];
        float ik = si[w][k];
        au0 += ws_u[k * D + lane]      * uk;
        au1 += ws_u[k * D + lane + 32] * uk;
        ai0 += ws_i[k * D + lane]      * ik;
        ai1 += ws_i[k * D + lane + 32] * ik;
    }

    float m = fmaxf(au0, au1);
    #pragma unroll
    for (int off = 16; off > 0; off >>= 1)
        m = fmaxf(m, __shfl_xor_sync(0xffffffffu, m, off));
    float ex0 = expf(au0 - m);
    float ex1 = expf(au1 - m);
    float ssum = ex0 + ex1;
    float tdot = ex0 * sigmoidf_(ai0) + ex1 * sigmoidf_(ai1);
    #pragma unroll
    for (int off = 16; off > 0; off >>= 1) {
        ssum += __shfl_xor_sync(0xffffffffu, ssum, off);
        tdot += __shfl_xor_sync(0xffffffffu, tdot, off);
    }

    if (lane == 0) {
        float xe = (xij[s] > 0) ? xij_emb1[item] : xij_emb0[item];
        out[s] = (1.0f - HYPER_X) * (tdot / ssum) + HYPER_X * sigmoidf_(xe);
    }
}

// ---------------------------------------------------------------------------
// kernel_launch
// ---------------------------------------------------------------------------
extern "C" void kernel_launch(void* const* d_in, const int* in_sizes, int n_in,
                              void* d_out, int out_size) {
    const float* emb_user = (const float*)d_in[0];
    const float* emb_item = (const float*)d_in[1];
    const float* w_user   = (const float*)d_in[2];
    const float* w_item   = (const float*)d_in[3];
    const float* xij_emb1 = (const float*)d_in[4];
    const float* xij_emb0 = (const float*)d_in[5];
    const float* g_val    = (const float*)d_in[6];
    const int*   g_row    = (const int*)d_in[7];
    const int*   g_col    = (const int*)d_in[8];
    const int*   users    = (const int*)d_in[9];
    const int*   items    = (const int*)d_in[10];
    const int*   xij      = (const int*)d_in[11];
    float*       out      = (float*)d_out;

    const int nnz = in_sizes[6];
    const int B   = in_sizes[9];

    unsigned *h0, *h1, *h2, *h3;
    cudaGetSymbolAddress((void**)&h0, g_h0);
    cudaGetSymbolAddress((void**)&h1, g_h1);
    cudaGetSymbolAddress((void**)&h2, g_h2);
    cudaGetSymbolAddress((void**)&h3, g_h3);

    const int qblocks = (nnz / 4 + 255) / 256 + 1;
    convert_mark_hist_kernel<<<qblocks, 256>>>((const float2*)emb_user,
                                               (const float2*)emb_item,
                                               users, items, B, g_row, nnz);
    scan_lookback_kernel<<<SCAN_NB, SCAN_BLK>>>();
    fill_kernel<<<qblocks, 256>>>(g_row, g_col, g_val, nnz);

    const int warps_per_block = 8;                 // 256 threads
    const int sblocks = (N_TOTAL + warps_per_block - 1) / warps_per_block;
    spmm_h_kernel<<<sblocks, 256>>>(h0, h1);
    spmm_h_kernel<<<sblocks, 256>>>(h1, h2);
    const int lblocks = (MAX_SAMPLED + warps_per_block - 1) / warps_per_block;
    spmm_list_kernel<<<lblocks, 256>>>(h2, h3);

    const int eblocks = (B + SAMPLES_PER_BLOCK - 1) / SAMPLES_PER_BLOCK;
    epilogue_kernel<<<eblocks, 256>>>(emb_user, emb_item, w_user, w_item,
                                      xij_emb1, xij_emb0, users, items, xij,
                                      out, B);
}

// round 16
// speedup vs baseline: 1.0027x; 1.0027x over previous
#include <cuda_runtime.h>
#include <cuda_bf16.h>

#define N_USERS 100000
#define N_ITEMS 50000
#define N_TOTAL (N_USERS + N_ITEMS)
#define D 64
#define DH 32                 // bf16x2 words per row (128B = one L2 line)
#define HYPER_X 0.5f
#define MAX_NNZ 2000000
#define MAX_SAMPLED 32768
#define SCAN_BLK 1024
#define SCAN_NB ((N_TOTAL + SCAN_BLK - 1) / SCAN_BLK)   // 147

// bf16x2 feature tables stored as raw uint32 words
__device__ unsigned g_h0[N_TOTAL * DH];   // converted input embeddings
__device__ unsigned g_h1[N_TOTAL * DH];
__device__ unsigned g_h2[N_TOTAL * DH];
__device__ unsigned g_h3[N_TOTAL * DH];

// CSR scratch. INVARIANT: g_deg, g_flag, g_blocksum, g_rowcount are ZERO at
// kernel_launch entry — zero-initialized at module load, re-zeroed at the end
// of every launch (inside epilogue_kernel), so graph replays are safe.
__device__ int  g_deg[N_TOTAL];
__device__ int  g_offs[N_TOTAL + 1];
__device__ int  g_rank[MAX_NNZ];         // per-edge within-row rank (from hist atomics)
__device__ int  g_blocksum[SCAN_NB];     // lookback slots: 0 = not ready, else agg+1
__device__ __align__(16) int2 g_csr[MAX_NNZ];   // {col, float_as_int(val)}

// sampled-row dedup for masked layer 3
__device__ int g_flag[N_TOTAL];
__device__ int g_rowlist[MAX_SAMPLED];
__device__ int g_rowcount;

// bf16x2 word -> 2 floats: pure ALU (SHF + LOP3), no CVT
__device__ __forceinline__ float2 bf2f(unsigned w) {
    float2 r;
    r.x = __uint_as_float(w << 16);
    r.y = __uint_as_float(w & 0xFFFF0000u);
    return r;
}
// 2 floats -> bf16x2 word (single cvt.rn.bf16x2.f32)
__device__ __forceinline__ unsigned f2bf(float a, float b) {
    __nv_bfloat162 p = __floats2bfloat162_rn(a, b);
    return *reinterpret_cast<unsigned*>(&p);
}

// ---------------------------------------------------------------------------
// FUSED: fp32->bf16 embedding convert + sampled-row mark + degree histogram.
// ---------------------------------------------------------------------------
__global__ void convert_mark_hist_kernel(const float2* __restrict__ eu,
                                         const float2* __restrict__ ei,
                                         const int* __restrict__ users,
                                         const int* __restrict__ items, int B,
                                         const int* __restrict__ row, int nnz) {
    const int i = blockIdx.x * blockDim.x + threadIdx.x;
    const int nthreads = gridDim.x * blockDim.x;

    if (i < B) {
        int u = users[i];
        if (atomicExch(&g_flag[u], 1) == 0) {
            int p = atomicAdd(&g_rowcount, 1);
            g_rowlist[p] = u;
        }
        int it = N_USERS + items[i];
        if (atomicExch(&g_flag[it], 1) == 0) {
            int p = atomicAdd(&g_rowcount, 1);
            g_rowlist[p] = it;
        }
    }

    int base = 4 * i;
    if (base + 3 < nnz) {
        int4 r4 = ((const int4*)row)[i];
        int4 k4;
        k4.x = atomicAdd(&g_deg[r4.x], 1);
        k4.y = atomicAdd(&g_deg[r4.y], 1);
        k4.z = atomicAdd(&g_deg[r4.z], 1);
        k4.w = atomicAdd(&g_deg[r4.w], 1);
        ((int4*)g_rank)[i] = k4;
    } else {
        for (int e = base; e < nnz; e++)
            g_rank[e] = atomicAdd(&g_deg[row[e]], 1);
    }

    const int total = N_TOTAL * DH;
    for (int k = i; k < total; k += nthreads) {
        float2 v = (k < N_USERS * DH) ? __ldg(&eu[k]) : __ldg(&ei[k - N_USERS * DH]);
        g_h0[k] = f2bf(v.x, v.y);
    }
}

// ---------------------------------------------------------------------------
// single-kernel exclusive scan with decoupled lookback (147 blocks, 1 wave)
// ---------------------------------------------------------------------------
__device__ __forceinline__ int block_exscan(int v, int* sh) {
    int lane = threadIdx.x & 31, wid = threadIdx.x >> 5;
    int incl = v;
    #pragma unroll
    for (int o = 1; o < 32; o <<= 1) {
        int n = __shfl_up_sync(0xffffffffu, incl, o);
        if (lane >= o) incl += n;
    }
    if (lane == 31) sh[wid] = incl;
    __syncthreads();
    if (wid == 0) {
        int w = sh[lane];
        #pragma unroll
        for (int o = 1; o < 32; o <<= 1) {
            int n = __shfl_up_sync(0xffffffffu, w, o);
            if (lane >= o) w += n;
        }
        sh[lane] = w;
    }
    __syncthreads();
    int warpoff = (wid > 0) ? sh[wid - 1] : 0;
    return warpoff + incl - v;
}

__global__ void scan_lookback_kernel() {
    __shared__ int sh[32];
    __shared__ int base_sh;
    const int t = threadIdx.x;
    const int i = blockIdx.x * SCAN_BLK + t;
    int v = (i < N_TOTAL) ? g_deg[i] : 0;
    int ex = block_exscan(v, sh);

    if (t == SCAN_BLK - 1) {
        atomicExch(&g_blocksum[blockIdx.x], ex + v + 1);
    }
    if (t == 0) base_sh = 0;
    __syncthreads();

    if (t < blockIdx.x) {
        int a;
        do { a = atomicAdd(&g_blocksum[t], 0); } while (a == 0);
        atomicAdd(&base_sh, a - 1);
    }
    __syncthreads();

    int exg = ex + base_sh;
    if (i < N_TOTAL) {
        g_offs[i] = exg;
        if (i == N_TOTAL - 1) g_offs[N_TOTAL] = exg + v;
    }
}

// ---------------------------------------------------------------------------
// CSR fill, ATOMIC-FREE: pos = offs[row] + rank (rank captured during hist).
// ---------------------------------------------------------------------------
__global__ void fill_kernel(const int* __restrict__ row,
                            const int* __restrict__ col,
                            const float* __restrict__ val, int nnz) {
    int t = blockIdx.x * blockDim.x + threadIdx.x;
    int base = 4 * t;
    if (base + 3 < nnz) {
        int4   r4 = ((const int4*)row)[t];
        int4   c4 = ((const int4*)col)[t];
        float4 v4 = ((const float4*)val)[t];
        int4   k4 = ((const int4*)g_rank)[t];
        int p0 = __ldg(&g_offs[r4.x]) + k4.x;
        int p1 = __ldg(&g_offs[r4.y]) + k4.y;
        int p2 = __ldg(&g_offs[r4.z]) + k4.z;
        int p3 = __ldg(&g_offs[r4.w]) + k4.w;
        g_csr[p0] = make_int2(c4.x, __float_as_int(v4.x));
        g_csr[p1] = make_int2(c4.y, __float_as_int(v4.y));
        g_csr[p2] = make_int2(c4.z, __float_as_int(v4.z));
        g_csr[p3] = make_int2(c4.w, __float_as_int(v4.w));
    } else {
        for (int e = base; e < nnz; e++) {
            int p = __ldg(&g_offs[row[e]]) + g_rank[e];
            g_csr[p] = make_int2(col[e], __float_as_int(val[e]));
        }
    }
}

// ---------------------------------------------------------------------------
// SpMM (bf16 storage, fp32 accumulate): 1 warp per row, 16 LANES PER EDGE.
// Per 2 edges: ONE meta LDG.64 (per-half address, same 128B line) + ONE
// gather LDG.64 per lane (16 lanes x 8B = full 128B row line) — halves the
// LSU dispatch count vs the 32-lane form. No shuffles in the loop; halves
// combined with 4 shfl_xor(16) once per row. Odd tail: clamp + zero val.
// ---------------------------------------------------------------------------
__device__ __forceinline__ void spmm_row_bf(
        int r, int lane,
        const unsigned* __restrict__ x, unsigned* __restrict__ y) {
    const int half = lane >> 4;       // which edge of the pair
    const int q    = lane & 15;       // 8-byte chunk within the row
    const int beg = g_offs[r];
    const int end = g_offs[r + 1];
    const int last = end - 1;

    float a0 = 0.f, a1 = 0.f, a2 = 0.f, a3 = 0.f;
    for (int j = beg; j < end; j += 2) {
        int e = min(j + half, last);               // branch-free odd-tail clamp
        int2 m = g_csr[e];                         // per-half meta (1 LDG/warp)
        float v = (j + half < end) ? __int_as_float(m.y) : 0.f;
        uint2 w = *(const uint2*)&x[(long)m.x * DH + 2 * q];   // 8B gather
        float2 lo = bf2f(w.x);
        float2 hi = bf2f(w.y);
        a0 += v * lo.x; a1 += v * lo.y;
        a2 += v * hi.x; a3 += v * hi.y;
    }
    // combine the two half-warp partial sums
    a0 += __shfl_xor_sync(0xffffffffu, a0, 16);
    a1 += __shfl_xor_sync(0xffffffffu, a1, 16);
    a2 += __shfl_xor_sync(0xffffffffu, a2, 16);
    a3 += __shfl_xor_sync(0xffffffffu, a3, 16);
    if (half == 0) {
        uint2 o;
        o.x = f2bf(a0, a1);
        o.y = f2bf(a2, a3);
        *(uint2*)&y[(long)r * DH + 2 * q] = o;
    }
}

__global__ void spmm_h_kernel(const unsigned* __restrict__ x,
                              unsigned* __restrict__ y) {
    const int lane = threadIdx.x & 31;
    const int r = (blockIdx.x * blockDim.x + threadIdx.x) >> 5;
    if (r >= N_TOTAL) return;
    spmm_row_bf(r, lane, x, y);
}

// layer 3: only sampled rows
__global__ void spmm_list_kernel(const unsigned* __restrict__ x,
                                 unsigned* __restrict__ y) {
    const int lane = threadIdx.x & 31;
    const int idx = (blockIdx.x * blockDim.x + threadIdx.x) >> 5;
    if (idx >= g_rowcount) return;
    const int r = g_rowlist[idx];
    spmm_row_bf(r, lane, x, y);
}

// ---------------------------------------------------------------------------
// Epilogue: e0 from fp32 inputs (exact), e1..e3 from bf16 tables.
// ALSO restores the zeroed-state invariant (fused cleanup).
// ---------------------------------------------------------------------------
#define SAMPLES_PER_BLOCK 8

__device__ __forceinline__ float sigmoidf_(float x) {
    return 1.0f / (1.0f + expf(-x));
}

__global__ void epilogue_kernel(const float* __restrict__ emb_user,
                                const float* __restrict__ emb_item,
                                const float* __restrict__ w_user,
                                const float* __restrict__ w_item,
                                const float* __restrict__ xij_emb1,
                                const float* __restrict__ xij_emb0,
                                const int* __restrict__ users,
                                const int* __restrict__ items,
                                const int* __restrict__ xij,
                                float* __restrict__ out,
                                int B) {
    __shared__ float ws_u[D * D];                 // transposed
    __shared__ float ws_i[D * D];
    __shared__ float su[SAMPLES_PER_BLOCK][D];
    __shared__ float si[SAMPLES_PER_BLOCK][D];

    // fused cleanup: restore zeroed invariant for next graph replay
    const int gi = blockIdx.x * blockDim.x + threadIdx.x;
    if (gi < N_TOTAL) { g_deg[gi] = 0; g_flag[gi] = 0; }
    if (gi < SCAN_NB) g_blocksum[gi] = 0;
    if (gi == 0) g_rowcount = 0;

    const int tid = threadIdx.x;
    for (int idx = tid; idx < D * D; idx += blockDim.x) {
        int d = idx >> 6, k = idx & 63;
        ws_u[k * D + d] = w_user[idx];
        ws_i[k * D + d] = w_item[idx];
    }

    const int w    = tid >> 5;
    const int lane = tid & 31;
    const int s    = blockIdx.x * SAMPLES_PER_BLOCK + w;

    int item = 0;
    if (s < B) {
        int urow = users[s];
        item = items[s];
        int irow = N_USERS + item;

        long uo = (long)urow * DH + lane;
        long io = (long)irow * DH + lane;
        float2 u0 = *(const float2*)&emb_user[(long)urow * D + 2 * lane];
        float2 i0 = *(const float2*)&emb_item[(long)item * D + 2 * lane];
        float2 u1 = bf2f(g_h1[uo]);
        float2 u2 = bf2f(g_h2[uo]);
        float2 u3 = bf2f(g_h3[uo]);
        float2 i1 = bf2f(g_h1[io]);
        float2 i2 = bf2f(g_h2[io]);
        float2 i3 = bf2f(g_h3[io]);
        su[w][2 * lane]     = 0.25f * (u0.x + u1.x + u2.x + u3.x);
        su[w][2 * lane + 1] = 0.25f * (u0.y + u1.y + u2.y + u3.y);
        si[w][2 * lane]     = 0.25f * (i0.x + i1.x + i2.x + i3.x);
        si[w][2 * lane + 1] = 0.25f * (i0.y + i1.y + i2.y + i3.y);
    }
    __syncthreads();
    if (s >= B) return;

    float au0 = 0.f, au1 = 0.f, ai0 = 0.f, ai1 = 0.f;
    #pragma unroll
    for (int k = 0; k < D; k++) {
        float uk = su[w][k];
        float ik = si[w][k];
        au0 += ws_u[k * D + lane]      * uk;
        au1 += ws_u[k * D + lane + 32] * uk;
        ai0 += ws_i[k * D + lane]      * ik;
        ai1 += ws_i[k * D + lane + 32] * ik;
    }

    float m = fmaxf(au0, au1);
    #pragma unroll
    for (int off = 16; off > 0; off >>= 1)
        m = fmaxf(m, __shfl_xor_sync(0xffffffffu, m, off));
    float ex0 = expf(au0 - m);
    float ex1 = expf(au1 - m);
    float ssum = ex0 + ex1;
    float tdot = ex0 * sigmoidf_(ai0) + ex1 * sigmoidf_(ai1);
    #pragma unroll
    for (int off = 16; off > 0; off >>= 1) {
        ssum += __shfl_xor_sync(0xffffffffu, ssum, off);
        tdot += __shfl_xor_sync(0xffffffffu, tdot, off);
    }

    if (lane == 0) {
        float xe = (xij[s] > 0) ? xij_emb1[item] : xij_emb0[item];
        out[s] = (1.0f - HYPER_X) * (tdot / ssum) + HYPER_X * sigmoidf_(xe);
    }
}

// ---------------------------------------------------------------------------
// kernel_launch
// ---------------------------------------------------------------------------
extern "C" void kernel_launch(void* const* d_in, const int* in_sizes, int n_in,
                              void* d_out, int out_size) {
    const float* emb_user = (const float*)d_in[0];
    const float* emb_item = (const float*)d_in[1];
    const float* w_user   = (const float*)d_in[2];
    const float* w_item   = (const float*)d_in[3];
    const float* xij_emb1 = (const float*)d_in[4];
    const float* xij_emb0 = (const float*)d_in[5];
    const float* g_val    = (const float*)d_in[6];
    const int*   g_row    = (const int*)d_in[7];
    const int*   g_col    = (const int*)d_in[8];
    const int*   users    = (const int*)d_in[9];
    const int*   items    = (const int*)d_in[10];
    const int*   xij      = (const int*)d_in[11];
    float*       out      = (float*)d_out;

    const int nnz = in_sizes[6];
    const int B   = in_sizes[9];

    unsigned *h0, *h1, *h2, *h3;
    cudaGetSymbolAddress((void**)&h0, g_h0);
    cudaGetSymbolAddress((void**)&h1, g_h1);
    cudaGetSymbolAddress((void**)&h2, g_h2);
    cudaGetSymbolAddress((void**)&h3, g_h3);

    const int qblocks = (nnz / 4 + 255) / 256 + 1;
    convert_mark_hist_kernel<<<qblocks, 256>>>((const float2*)emb_user,
                                               (const float2*)emb_item,
                                               users, items, B, g_row, nnz);
    scan_lookback_kernel<<<SCAN_NB, SCAN_BLK>>>();
    fill_kernel<<<qblocks, 256>>>(g_row, g_col, g_val, nnz);

    const int warps_per_block = 8;                 // 256 threads
    const int sblocks = (N_TOTAL + warps_per_block - 1) / warps_per_block;
    spmm_h_kernel<<<sblocks, 256>>>(h0, h1);
    spmm_h_kernel<<<sblocks, 256>>>(h1, h2);
    const int lblocks = (MAX_SAMPLED + warps_per_block - 1) / warps_per_block;
    spmm_list_kernel<<<lblocks, 256>>>(h2, h3);

    const int eblocks = (B + SAMPLES_PER_BLOCK - 1) / SAMPLES_PER_BLOCK;
    epilogue_kernel<<<eblocks, 256>>>(emb_user, emb_item, w_user, w_item,
                                      xij_emb1, xij_emb0, users, items, xij,
                                      out, B);
}